// round 16
// baseline (speedup 1.0000x reference)
#include <cuda_runtime.h>
#include <cstdint>

// Problem constants
#define SIN   512          // input H=W
#define HW    128          // resized H=W and volume H=W
#define ND    128          // depth bins
#define NB    8            // batch

typedef unsigned long long ull;

// Packed f32x2 helpers (sm_103a FFMA2 path)
__device__ __forceinline__ ull pk2(float lo, float hi) {
    ull r; asm("mov.b64 %0, {%1, %2};" : "=l"(r) : "f"(lo), "f"(hi)); return r;
}
__device__ __forceinline__ float2 upk2(ull v) {
    float2 f; asm("mov.b64 {%0, %1}, %2;" : "=f"(f.x), "=f"(f.y) : "l"(v)); return f;
}
__device__ __forceinline__ ull ffma2(ull a, ull b, ull c) {
    ull d; asm("fma.rn.f32x2 %0, %1, %2, %3;" : "=l"(d) : "l"(a), "l"(b), "l"(c));
    return d;
}

// Scratch: per-pixel {xray_resized, (float)d_idx}
__device__ float2 g_pix[NB * HW * HW];

// ---------------------------------------------------------------------------
// Kernel A: jax.image.resize(bilinear, antialias) 512->128 for both arrays,
// fused with d_idx computation.  (R1 version, verbatim)
// ---------------------------------------------------------------------------
__global__ __launch_bounds__(128) void resize_kernel(
    const float* __restrict__ depth, const float* __restrict__ xray)
{
    __shared__ float2 hrow[SIN];   // H-contracted row at this output row: {d, x}

    const int ho  = blockIdx.x;    // 0..127
    const int b   = blockIdx.y;    // 0..7
    const int tid = threadIdx.x;   // 128 threads

    const float BW[8] = {0.125f, 0.375f, 0.625f, 0.875f,
                         0.875f, 0.625f, 0.375f, 0.125f};

    const int ih0 = 4 * ho - 2;

    float whn[8]; float hs = 0.f;
    #pragma unroll
    for (int k = 0; k < 8; k++) {
        int ih = ih0 + k;
        float w = (ih >= 0 && ih < SIN) ? BW[k] : 0.f;
        whn[k] = w; hs += w;
    }
    #pragma unroll
    for (int k = 0; k < 8; k++) whn[k] = __fdiv_rn(whn[k], hs);

    const float* dbase = depth + (size_t)b * SIN * SIN;
    const float* xbase = xray  + (size_t)b * SIN * SIN;

    {
        const int c0 = tid * 4;
        float4 ad = make_float4(0.f, 0.f, 0.f, 0.f);
        float4 ax = make_float4(0.f, 0.f, 0.f, 0.f);
        #pragma unroll
        for (int kh = 0; kh < 8; kh++) {
            if (whn[kh] != 0.f) {
                const int ih = ih0 + kh;
                const float4 dv = *(const float4*)(dbase + (size_t)ih * SIN + c0);
                const float4 xv = *(const float4*)(xbase + (size_t)ih * SIN + c0);
                const float w = whn[kh];
                ad.x = fmaf(w, dv.x, ad.x); ad.y = fmaf(w, dv.y, ad.y);
                ad.z = fmaf(w, dv.z, ad.z); ad.w = fmaf(w, dv.w, ad.w);
                ax.x = fmaf(w, xv.x, ax.x); ax.y = fmaf(w, xv.y, ax.y);
                ax.z = fmaf(w, xv.z, ax.z); ax.w = fmaf(w, xv.w, ax.w);
            }
        }
        hrow[c0 + 0] = make_float2(ad.x, ax.x);
        hrow[c0 + 1] = make_float2(ad.y, ax.y);
        hrow[c0 + 2] = make_float2(ad.z, ax.z);
        hrow[c0 + 3] = make_float2(ad.w, ax.w);
    }
    __syncthreads();

    const int wo  = tid;
    const int iw0 = 4 * wo - 2;

    float wwn[8]; float ws = 0.f;
    #pragma unroll
    for (int k = 0; k < 8; k++) {
        int iw = iw0 + k;
        float w = (iw >= 0 && iw < SIN) ? BW[k] : 0.f;
        wwn[k] = w; ws += w;
    }
    #pragma unroll
    for (int k = 0; k < 8; k++) wwn[k] = __fdiv_rn(wwn[k], ws);

    float ad = 0.f, ax = 0.f;
    #pragma unroll
    for (int k = 0; k < 8; k++) {
        if (wwn[k] != 0.f) {
            float2 p = hrow[iw0 + k];
            ad = fmaf(wwn[k], p.x, ad);
            ax = fmaf(wwn[k], p.y, ax);
        }
    }

    // d_idx = clip(int32((d/100)*127), 0, 127) — IEEE ops to match reference
    float nd = __fdiv_rn(ad, 100.0f);
    int di = (int)__fmul_rn(nd, 127.0f);
    di = min(max(di, 0), ND - 1);

    g_pix[((size_t)b * HW + ho) * HW + wo] = make_float2(ax, (float)di);
}

// ---------------------------------------------------------------------------
// Kernel B (R16): pure gather with clamped-QUARTIC profile + packed f32x2.
//   out[b,d,h,w] = sum over 3x3 nbhd of x_n * C(|d - di_n|)
//   C = quartic exact at a=0..3 with C(4)=0, evaluated at a=min(|d-di|,4)
//   -> no FSETP/SEL mask, single FMNMX per tap, FFMA2 for column pairs.
// Rows d=0 / d=127 recomputed once after the main loop with the edge quartic
// (box tap outside the volume dropped) — exact for any input, no fallback.
// ---------------------------------------------------------------------------
__global__ __launch_bounds__(256) void gather_pool_kernel(float* __restrict__ out)
{
    __shared__ float2 pix[180];     // 10x18 halo {x, d_idx}
    __shared__ int    srange[2];    // [0]=min di, [1]=max di

    const int tid = threadIdx.x;    // 0..255
    const int w0  = blockIdx.x * 16;
    const int h0  = blockIdx.y * 8;
    const int b   = blockIdx.z;

    // Interior quartic: C(a) exact at a=0..3, C(4)=0 (C = box3(gauss5)/27)
    const float K4f = -0.0013033148265782292f;
    const float K3f =  0.013512938242255463f;
    const float K2f = -0.04120828915412581f;
    const float K1f =  0.011546985128225586f;
    const float K0f =  0.08196523405278766f;
    // Edge quartic (d==0 or d==127): CE(a) = (g(a)+g(a-1))/27, CE(4)=0
    const float E4f = -0.001403915948130981f;
    const float E3f =  0.015354352440725033f;
    const float E2f = -0.05224795525495059f;
    const float E1f =  0.03829751876235654f;
    const float E0f =  0.05950113554491235f;

    const float4 z4 = make_float4(0.f, 0.f, 0.f, 0.f);

    // Mapping: lane g -> column quad, warp -> depth phase (d == dwarp mod 8)
    const int g     = tid & 31;     // quad index 0..31
    const int dwarp = tid >> 5;     // 0..7
    const int qh    = g >> 2;       // 0..7   (h within tile)
    const int qw4   = (g & 3) * 4;  // 0,4,8,12 (first w of quad)

    // Phase A: stage halo pixels; init range.
    float2 q = make_float2(0.f, 64.f);
    bool valid = false;
    if (tid < 180) {
        const int ph = h0 + tid / 18 - 1;
        const int pw = w0 + tid % 18 - 1;
        if (ph >= 0 && ph < HW && pw >= 0 && pw < HW) {
            q = g_pix[((size_t)b * HW + ph) * HW + pw];
            valid = true;
        }
        pix[tid] = q;
    }
    if (tid == 0) { srange[0] = ND - 1; srange[1] = 0; }
    __syncthreads();

    // Phase B: min/max over valid halo d_idx.
    if (valid) {
        const int di = (int)q.y;
        atomicMin(&srange[0], di);
        atomicMax(&srange[1], di);
    }
    __syncthreads();

    const int smin = srange[0], smax = srange[1];
    const int olo  = max(0, smin - 3);
    const int ohi  = min(ND - 1, smax + 3);

    // Load the 18 neighbors (3 h-rows x 6 w-positions) for this quad.
    float ndi[18];
    ull   nxp[9];                   // nx packed in column pairs
    #pragma unroll
    for (int r = 0; r < 3; r++) {
        #pragma unroll
        for (int cp = 0; cp < 3; cp++) {
            const float2 qa = pix[(qh + r) * 18 + (qw4 + cp * 2)];
            const float2 qb = pix[(qh + r) * 18 + (qw4 + cp * 2 + 1)];
            ndi[r * 6 + cp * 2]     = qa.y;
            ndi[r * 6 + cp * 2 + 1] = qb.y;
            nxp[r * 3 + cp] = pk2(qa.x, qb.x);
        }
    }

    // Packed interior constants (hoisted)
    const ull K4p = pk2(K4f, K4f);
    const ull K3p = pk2(K3f, K3f);
    const ull K2p = pk2(K2f, K2f);
    const ull K1p = pk2(K1f, K1f);
    const ull K0p = pk2(K0f, K0f);

    const size_t obase =
        (size_t)b * ND * HW * HW + (size_t)(h0 + qh) * HW + (w0 + qw4);

    #pragma unroll
    for (int i = 0; i < 16; i++) {
        const int d = dwarp + 8 * i;            // warp-uniform depth
        float4 o = z4;
        if (d >= olo && d <= ohi) {             // warp-uniform branch
            const float df = (float)d;
            ull acc0 = 0ull, acc1 = 0ull, acc2 = 0ull;
            #pragma unroll
            for (int r = 0; r < 3; r++) {
                #pragma unroll
                for (int cp = 0; cp < 3; cp++) {
                    const int j = r * 6 + cp * 2;
                    const float a0 = fminf(fabsf(df - ndi[j]),     4.0f);
                    const float a1 = fminf(fabsf(df - ndi[j + 1]), 4.0f);
                    const ull ap = pk2(a0, a1);
                    ull pp = ffma2(ap, K4p, K3p);
                    pp = ffma2(ap, pp, K2p);
                    pp = ffma2(ap, pp, K1p);
                    pp = ffma2(ap, pp, K0p);
                    const ull nx2 = nxp[r * 3 + cp];
                    if (cp == 0)      acc0 = ffma2(nx2, pp, acc0);
                    else if (cp == 1) acc1 = ffma2(nx2, pp, acc1);
                    else              acc2 = ffma2(nx2, pp, acc2);
                }
            }
            const float2 s01 = upk2(acc0);
            const float2 s23 = upk2(acc1);
            const float2 s45 = upk2(acc2);
            const float t12 = s01.y + s23.x;
            const float t34 = s23.y + s45.x;
            o.x = s01.x + t12;
            o.y = t12 + s23.y;
            o.z = s23.x + t34;
            o.w = t34 + s45.y;
        }
        *(float4*)&out[obase + (size_t)d * HW * HW] = o;
    }

    // Edge depths: recompute d=0 (warp 0) / d=127 (warp 7) with the edge
    // quartic and overwrite. Only runs when the live range touches the
    // boundary; same thread overwrites its own earlier store.
    const bool lo_edge = (dwarp == 0) && (olo == 0);
    const bool hi_edge = (dwarp == 7) && (ohi == ND - 1);
    if (lo_edge || hi_edge) {
        const int d = lo_edge ? 0 : (ND - 1);
        const float df = (float)d;
        float s[6];
        #pragma unroll
        for (int cp = 0; cp < 3; cp++) {
            float sa = 0.f, sb = 0.f;
            #pragma unroll
            for (int r = 0; r < 3; r++) {
                const int j = r * 6 + cp * 2;
                const float2 nx2 = upk2(nxp[r * 3 + cp]);
                float a = fminf(fabsf(df - ndi[j]), 4.0f);
                float pe = fmaf(a, E4f, E3f);
                pe = fmaf(a, pe, E2f);
                pe = fmaf(a, pe, E1f);
                pe = fmaf(a, pe, E0f);
                sa = fmaf(nx2.x, pe, sa);
                a = fminf(fabsf(df - ndi[j + 1]), 4.0f);
                pe = fmaf(a, E4f, E3f);
                pe = fmaf(a, pe, E2f);
                pe = fmaf(a, pe, E1f);
                pe = fmaf(a, pe, E0f);
                sb = fmaf(nx2.y, pe, sb);
            }
            s[cp * 2] = sa; s[cp * 2 + 1] = sb;
        }
        float4 o;
        o.x = s[0] + s[1] + s[2];
        o.y = s[1] + s[2] + s[3];
        o.z = s[2] + s[3] + s[4];
        o.w = s[3] + s[4] + s[5];
        *(float4*)&out[obase + (size_t)d * HW * HW] = o;
    }
}

// ---------------------------------------------------------------------------
extern "C" void kernel_launch(void* const* d_in, const int* in_sizes, int n_in,
                              void* d_out, int out_size)
{
    const float* depth = (const float*)d_in[0];
    const float* xray  = (const float*)d_in[1];
    float* out = (float*)d_out;

    // Kernel A: resize + d_idx
    resize_kernel<<<dim3(HW, NB), 128>>>(depth, xray);

    // Kernel B: pure-gather splat + 3x3x3 box average (quartic, f32x2)
    gather_pool_kernel<<<dim3(HW / 16, HW / 8, NB), 256>>>(out);
}